// round 11
// baseline (speedup 1.0000x reference)
#include <cuda_runtime.h>
#include <cuda_fp16.h>
#include <cstdint>

#define MR     32
#define NCOLS  10000
#define KDIM   10000
#define NB     157        // column blocks of 64 (157*64 = 10048 padded)
#define BN     64
#define KCH    625        // k-chunks of 16
#define NPCH   628        // padded chunk count for Y buffers
#define STAGES 24
#define KSPLIT 8
#define STGB   9216       // bytes per pipeline stage (A 6144 + Y 3072)
#define SMEMSZ (STAGES * STGB)
#define INV2048 (1.0f/2048.0f)

// ---------------- device scratch (allocation-free) ----------------
__device__ __align__(16) __half g_Apk[(size_t)NB * KCH * 2048];     // ~402 MB
__device__ __align__(16) __half g_Yp[2][(size_t)NPCH * 1024];
__device__ __align__(16) float  g_Zp[(size_t)KSPLIT * NB * 2048];   // split-K partials
__device__ float  g_B[NB * BN * MR];
__device__ float  g_Wp[MR * MR];
__device__ int    g_cnt[NB];                                        // zero-init; self-resetting

// ---------------- helpers ----------------
__device__ __forceinline__ void cpa16(uint32_t d, const void* s) {
    asm volatile("cp.async.cg.shared.global [%0], [%1], 16;" :: "r"(d), "l"(s));
}
__device__ __forceinline__ void ldm4(uint32_t* r, uint32_t a) {
    asm volatile("ldmatrix.sync.aligned.m8n8.x4.shared.b16 {%0,%1,%2,%3}, [%4];"
        : "=r"(r[0]), "=r"(r[1]), "=r"(r[2]), "=r"(r[3]) : "r"(a));
}
__device__ __forceinline__ void mma_(float* c, const uint32_t* a, uint32_t b0, uint32_t b1) {
    asm volatile("mma.sync.aligned.m16n8k16.row.col.f32.f16.f16.f32 "
        "{%0,%1,%2,%3}, {%4,%5,%6,%7}, {%8,%9}, {%0,%1,%2,%3};"
        : "+f"(c[0]), "+f"(c[1]), "+f"(c[2]), "+f"(c[3])
        : "r"(a[0]), "r"(a[1]), "r"(a[2]), "r"(a[3]), "r"(b0), "r"(b1));
}
__device__ __forceinline__ void hilo(float v, __half& h, __half& l) {
    h = __float2half_rn(v);
    l = __float2half_rn((v - __half2float(h)) * 2048.0f);
}

// ---------------- 1. W projection (verified) ----------------
__global__ void k_project(const float* __restrict__ W) {
    int r = threadIdx.x;
    if (r >= MR) return;
    float a[32], u[32];
    float s = 0.0f;
    for (int i = 0; i < 32; i++) { a[i] = W[r * 32 + i]; u[i] = fabsf(a[i]); s += u[i]; }
    const float v = 0.99f;
    if (s > v) {
        for (int i = 1; i < 32; i++) {
            float key = u[i]; int j = i - 1;
            while (j >= 0 && u[j] < key) { u[j + 1] = u[j]; j--; }
            u[j + 1] = key;
        }
        float cs = 0.0f; int rho = 0;
        for (int i = 0; i < 32; i++) {
            cs += u[i];
            if (u[i] - (cs - v) / (float)(i + 1) > 0.0f) rho++;
        }
        float cs2 = 0.0f;
        for (int i = 0; i < rho; i++) cs2 += u[i];
        float theta = (cs2 - v) / (float)rho;
        for (int i = 0; i < 32; i++) {
            float m = fmaxf(fabsf(a[i]) - theta, 0.0f);
            a[i] = (a[i] > 0.0f) ? m : ((a[i] < 0.0f) ? -m : 0.0f);
        }
    }
    for (int i = 0; i < 32; i++) g_Wp[r * 32 + i] = a[i];
}

// ---------------- 2. Convert A -> blocked fp16 hi/lo (verified) ----------------
__global__ void k_convA(const float* __restrict__ A) {
    __shared__ __align__(16) float sA[16][68];
    int b  = blockIdx.x;               // nb*KCH + kc
    int nb = b / KCH, kc = b % KCH;
    int t  = threadIdx.x;
    int k0 = kc * 16, c0 = nb * BN;
    for (int e = t; e < 1024; e += 128) {
        int kk = e >> 6, c = e & 63;
        int gc = c0 + c;
        float v0 = 0.0f;
        if (gc < NCOLS) v0 = A[(size_t)(k0 + kk) * NCOLS + gc];
        sA[kk][c] = v0;
    }
    __syncthreads();
    __half* dst = &g_Apk[(size_t)b * 2048];
    for (int e = t; e < 1024; e += 128) {
        int c = e >> 4, kk = e & 15;
        __half h, l; hilo(sA[kk][c], h, l);
        dst[e] = h;
        dst[1024 + e] = l;
    }
}

// ---------------- 3. T = Omega_1 @ U -> Y[0] (verified) ----------------
__global__ void k_T(const float* __restrict__ Om1, const float* __restrict__ U) {
    __shared__ float sOm[MR * 64];
    int t = threadIdx.x;
    for (int i = t; i < MR * 64; i += 128) sOm[i] = Om1[i];
    __syncthreads();
    int kc = blockIdx.x;
    __half* dst = &g_Yp[0][(size_t)kc * 1024];
    for (int e = t; e < 512; e += 128) {
        int m = e >> 4, kk = e & 15;
        int k = kc * 16 + kk;
        float v = 0.f;
        #pragma unroll
        for (int p = 0; p < 64; p++) v += sOm[m * 64 + p] * U[(size_t)p * NCOLS + k];
        __half h, l; hilo(v, h, l);
        dst[m * 16 + kk] = h;
        dst[512 + m * 16 + kk] = l;
    }
}

// ---------------- 4. Fused Picard pass: 256 thr, 24-deep pipeline ------------
__global__ void __launch_bounds__(256, 1)
k_iter(const int* __restrict__ fw, float* __restrict__ out,
       int it, int src, int writeB, int useB) {
    extern __shared__ __align__(16) unsigned char sBuf[];   // STAGES*STGB dynamic
    __shared__ int sLast;

    const int t = threadIdx.x;
    const int nb = blockIdx.x % NB;
    const int sp = blockIdx.x / NB;
    const int w = t >> 5, lane = t & 31;
    const int mg = w >> 1;        // m-group: 4 groups of 16 A-cols
    const int nh = w & 1;         // n-half : 2 halves of 16 Y-rows

    const int fwv = *fw;
    if (it > fwv) return;

    const int kbeg = (sp * KCH) / KSPLIT;
    const int kend = ((sp + 1) * KCH) / KSPLIT;

    const __half* Asrc = &g_Apk[(size_t)nb * KCH * 2048];
    const __half* Ysrc = g_Yp[src];
    const uint32_t base = (uint32_t)__cvta_generic_to_shared(sBuf);

    // cp.async granule mapping: A 256 granules -> 1/thread; Y 128 -> threads<128
    const int aH = t >> 7, aI = t & 127;
    const int aC = aI >> 1, aS = aI & 1;
    const uint32_t dA = ((aH * 64 + aC) * 24 + aS * 8) * 2;
    const int     sA = aH * 1024 + aC * 16 + aS * 8;
    const int yH = (t >> 6) & 1, yI = t & 63;
    const int yM2 = yI >> 1, yS = yI & 1;
    const uint32_t dY = ((yH * 32 + yM2) * 24 + yS * 8) * 2;
    const int     sY = yH * 512 + yM2 * 16 + yS * 8;
    const bool hasY = (t < 128);

    // ldmatrix per-lane byte offsets
    const int tl = lane >> 3, rl = lane & 7;
    const int aRow = mg * 16 + ((tl & 1) << 3) + rl;
    const int aKo  = (tl >> 1) << 3;
    const uint32_t offAhi = (uint32_t)((aRow)      * 24 + aKo) * 2;
    const uint32_t offAlo = (uint32_t)((64 + aRow) * 24 + aKo) * 2;
    const int yM  = ((tl >> 1) << 3) + rl;
    const int yKo = (tl & 1) << 3;
    const uint32_t offYh = (uint32_t)((nh * 16 + yM)      * 24 + yKo) * 2;
    const uint32_t offYl = (uint32_t)((32 + nh * 16 + yM) * 24 + yKo) * 2;

    auto issue = [&](int kc2) {
        int buf = (kc2 - kbeg) % STAGES;
        uint32_t ab = base + buf * STGB;
        cpa16(ab + dA, Asrc + (size_t)kc2 * 2048 + sA);
        if (hasY) cpa16(ab + 6144 + dY, Ysrc + (size_t)kc2 * 1024 + sY);
    };

    // prologue: STAGES-1 chunks, one group each
    for (int p = 0; p < STAGES - 1; p++) {
        issue(kbeg + p);
        asm volatile("cp.async.commit_group;");
    }

    float Cm[2][4], Cs[2][4];
    #pragma unroll
    for (int j = 0; j < 2; j++)
        #pragma unroll
        for (int q = 0; q < 4; q++) { Cm[j][q] = 0.f; Cs[j][q] = 0.f; }

    for (int c = kbeg; c < kend; c++) {
        asm volatile("cp.async.wait_group %0;" :: "n"(STAGES - 2));
        __syncthreads();
        int nkc = c + STAGES - 1;
        if (nkc < kend) issue(nkc);
        asm volatile("cp.async.commit_group;");

        int buf = (c - kbeg) % STAGES;
        uint32_t ab = base + buf * STGB;
        uint32_t yb = ab + 6144;

        uint32_t Ah[4], Al[4], Yh[4], Yl[4];
        ldm4(Ah, ab + offAhi);
        ldm4(Al, ab + offAlo);
        ldm4(Yh, yb + offYh);
        ldm4(Yl, yb + offYl);

        mma_(Cm[0], Ah, Yh[0], Yh[1]);
        mma_(Cm[1], Ah, Yh[2], Yh[3]);
        mma_(Cs[0], Ah, Yl[0], Yl[1]);
        mma_(Cs[1], Ah, Yl[2], Yl[3]);
        mma_(Cs[0], Al, Yh[0], Yh[1]);
        mma_(Cs[1], Al, Yh[2], Yh[3]);
    }
    asm volatile("cp.async.wait_group 0;");
    __syncthreads();

    // scatter C frags -> sZ[c][m]  (overlay on drained pipeline smem)
    float (*sZ)[33] = (float (*)[33])sBuf;
    {
        const int g = lane >> 2, i2 = (lane & 3) << 1;
        const int cc = mg * 16 + g;
        #pragma unroll
        for (int j = 0; j < 2; j++) {
            int m = nh * 16 + j * 8 + i2;
            sZ[cc][m]         = Cm[j][0] + Cs[j][0] * INV2048;
            sZ[cc][m + 1]     = Cm[j][1] + Cs[j][1] * INV2048;
            sZ[cc + 8][m]     = Cm[j][2] + Cs[j][2] * INV2048;
            sZ[cc + 8][m + 1] = Cm[j][3] + Cs[j][3] * INV2048;
        }
    }
    __syncthreads();

    // store partial Z (coalesced float4, 8 floats per thread)
    {
        float* gp = &g_Zp[((size_t)(sp * NB + nb)) * 2048];
        #pragma unroll
        for (int q = 0; q < 2; q++) {
            int idx = t * 8 + q * 4;
            int cc = idx >> 5, m = idx & 31;
            float4 v = make_float4(sZ[cc][m], sZ[cc][m + 1], sZ[cc][m + 2], sZ[cc][m + 3]);
            *reinterpret_cast<float4*>(gp + idx) = v;
        }
    }
    __threadfence();
    __syncthreads();
    if (t == 0) {
        int old = atomicAdd(&g_cnt[nb], 1);
        sLast = (old == KSPLIT - 1);
    }
    __syncthreads();
    if (!sLast) return;

    // ---- ticket CTA: reduce partials + epilogue ----
    float* sWp = (float*)(sBuf + 64 * 33 * 4);   // after sZ, within drained smem
    for (int i = t; i < MR * MR; i += 256) sWp[i] = g_Wp[i];

    const int col = t >> 2, r0 = (t & 3) << 3;   // 4 threads/col, 8 rows each
    const int gcol = nb * BN + col;
    float z[8];
    #pragma unroll
    for (int q = 0; q < 2; q++) {
        float4 acc = make_float4(0.f, 0.f, 0.f, 0.f);
        #pragma unroll
        for (int s2 = 0; s2 < KSPLIT; s2++) {
            const float4* p = reinterpret_cast<const float4*>(
                &g_Zp[((size_t)(s2 * NB + nb)) * 2048 + col * 32 + r0 + q * 4]);
            float4 v = __ldcg(p);
            acc.x += v.x; acc.y += v.y; acc.z += v.z; acc.w += v.w;
        }
        z[q * 4 + 0] = acc.x; z[q * 4 + 1] = acc.y;
        z[q * 4 + 2] = acc.z; z[q * 4 + 3] = acc.w;
    }

    float* Bp = &g_B[(nb * BN + col) * MR];
    const bool writeOut = (it == fwv);
    const bool writeY   = (it < fwv);

    #pragma unroll
    for (int r = 0; r < 8; r++) {
        int rr = r0 + r;
        float zz = z[r];
        if (useB)   zz += Bp[rr];
        if (writeB) Bp[rr] = zz;
        float xv = fmaxf(zz, 0.0f);
        if (writeOut && gcol < NCOLS) out[(size_t)rr * NCOLS + gcol] = xv;
        sZ[col][rr] = xv;
    }
    __syncthreads();

    if (writeY) {
        int kc = gcol >> 4, kk = gcol & 15;
        __half* Yd = g_Yp[src ^ 1] + (size_t)kc * 1024;
        #pragma unroll
        for (int r = 0; r < 8; r++) {
            int rr = r0 + r;
            float y = 0.f;
            #pragma unroll
            for (int j = 0; j < MR; j++) y += sWp[rr * MR + j] * sZ[col][j];
            __half h, l; hilo(y, h, l);
            Yd[rr * 16 + kk] = h;
            Yd[512 + rr * 16 + kk] = l;
        }
    }
    if (t == 0) g_cnt[nb] = 0;   // reset for next pass / replay
}

// ---------------- launch ----------------
// Inputs: W, Omega_1, Omega_2, X_0, A, U, fw_mitr
extern "C" void kernel_launch(void* const* d_in, const int* in_sizes, int n_in,
                              void* d_out, int out_size) {
    const float* W   = (const float*)d_in[0];
    const float* Om1 = (const float*)d_in[1];
    const float* A   = (const float*)d_in[4];
    const float* U   = (const float*)d_in[5];
    const int*   fw  = (const int*)  d_in[6];
    float*       out = (float*)d_out;

    static int attrDone = 0;
    if (!attrDone) {
        cudaFuncSetAttribute(k_iter, cudaFuncAttributeMaxDynamicSharedMemorySize, SMEMSZ);
        attrDone = 1;
    }

    k_project<<<1, 32>>>(W);
    k_convA<<<NB * KCH, 128>>>(A);
    k_T<<<KCH, 128>>>(Om1, U);

    // it = 1: Z = T@A = b ; B := Z ; X1 = relu(b) ; Y1 = Wp@X1
    k_iter<<<NB * KSPLIT, 256, SMEMSZ>>>(fw, out, 1, 0, 1, 0);
    // it = 2..30
    for (int it = 2; it <= 30; it++)
        k_iter<<<NB * KSPLIT, 256, SMEMSZ>>>(fw, out, it, (it - 1) & 1, 0, 1);
}

// round 13
// speedup vs baseline: 1.3424x; 1.3424x over previous
#include <cuda_runtime.h>
#include <cuda_fp16.h>
#include <cstdint>

#define MR     32
#define NCOLS  10000
#define KDIM   10000
#define NB     79         // column blocks of 128 (79*128 = 10112 padded)
#define BN     128
#define KCH    625        // k-chunks of 16
#define NPCH   632        // padded chunk count for Y buffers (10112/16)
#define STAGES 7
#define KSPLIT 16
#define STGB   15360      // bytes per stage: A (2*128*24*2=12288) + Y (2*32*24*2=3072)
#define SMEMSZ (STAGES * STGB)
#define INV2048 (1.0f/2048.0f)

// ---------------- device scratch (allocation-free) ----------------
// Per (nb,kc) chunk: 2048 hi halves [c][kk] then 2048 lo halves.  ~404 MB
__device__ __align__(16) __half g_Apk[(size_t)NB * KCH * 4096];
__device__ __align__(16) __half g_Yp[2][(size_t)NPCH * 1024];
__device__ __align__(16) float  g_Zp[(size_t)KSPLIT * NB * 4096];   // split-K partials
__device__ float  g_B[NB * BN * MR];
__device__ float  g_Wp[MR * MR];
__device__ int    g_cnt[NB];                                        // zero-init; self-resetting

// ---------------- helpers ----------------
__device__ __forceinline__ void cpa16(uint32_t d, const void* s) {
    asm volatile("cp.async.cg.shared.global [%0], [%1], 16;" :: "r"(d), "l"(s));
}
__device__ __forceinline__ void ldm4(uint32_t* r, uint32_t a) {
    asm volatile("ldmatrix.sync.aligned.m8n8.x4.shared.b16 {%0,%1,%2,%3}, [%4];"
        : "=r"(r[0]), "=r"(r[1]), "=r"(r[2]), "=r"(r[3]) : "r"(a));
}
__device__ __forceinline__ void mma_(float* c, const uint32_t* a, uint32_t b0, uint32_t b1) {
    asm volatile("mma.sync.aligned.m16n8k16.row.col.f32.f16.f16.f32 "
        "{%0,%1,%2,%3}, {%4,%5,%6,%7}, {%8,%9}, {%0,%1,%2,%3};"
        : "+f"(c[0]), "+f"(c[1]), "+f"(c[2]), "+f"(c[3])
        : "r"(a[0]), "r"(a[1]), "r"(a[2]), "r"(a[3]), "r"(b0), "r"(b1));
}
__device__ __forceinline__ void hilo(float v, __half& h, __half& l) {
    h = __float2half_rn(v);
    l = __float2half_rn((v - __half2float(h)) * 2048.0f);
}

// ---------------- 1. W projection (verified) ----------------
__global__ void k_project(const float* __restrict__ W) {
    int r = threadIdx.x;
    if (r >= MR) return;
    float a[32], u[32];
    float s = 0.0f;
    for (int i = 0; i < 32; i++) { a[i] = W[r * 32 + i]; u[i] = fabsf(a[i]); s += u[i]; }
    const float v = 0.99f;
    if (s > v) {
        for (int i = 1; i < 32; i++) {
            float key = u[i]; int j = i - 1;
            while (j >= 0 && u[j] < key) { u[j + 1] = u[j]; j--; }
            u[j + 1] = key;
        }
        float cs = 0.0f; int rho = 0;
        for (int i = 0; i < 32; i++) {
            cs += u[i];
            if (u[i] - (cs - v) / (float)(i + 1) > 0.0f) rho++;
        }
        float cs2 = 0.0f;
        for (int i = 0; i < rho; i++) cs2 += u[i];
        float theta = (cs2 - v) / (float)rho;
        for (int i = 0; i < 32; i++) {
            float m = fmaxf(fabsf(a[i]) - theta, 0.0f);
            a[i] = (a[i] > 0.0f) ? m : ((a[i] < 0.0f) ? -m : 0.0f);
        }
    }
    for (int i = 0; i < 32; i++) g_Wp[r * 32 + i] = a[i];
}

// ---------------- 2. Convert A -> blocked fp16 hi/lo, BN=128 ----------------
__global__ void k_convA(const float* __restrict__ A) {
    __shared__ __align__(16) float sA[16][132];
    int b  = blockIdx.x;               // nb*KCH + kc
    int nb = b / KCH, kc = b % KCH;
    int t  = threadIdx.x;
    int k0 = kc * 16, c0 = nb * BN;
    for (int e = t; e < 2048; e += 128) {
        int kk = e >> 7, c = e & 127;          // consecutive threads -> consecutive gc
        int gc = c0 + c;
        float v0 = 0.0f;
        if (gc < NCOLS) v0 = A[(size_t)(k0 + kk) * NCOLS + gc];
        sA[kk][c] = v0;
    }
    __syncthreads();
    __half* dst = &g_Apk[(size_t)b * 4096];
    for (int e = t; e < 2048; e += 128) {
        int c = e >> 4, kk = e & 15;
        __half h, l; hilo(sA[kk][c], h, l);
        dst[e] = h;
        dst[2048 + e] = l;
    }
}

// ---------------- 3. T = Omega_1 @ U -> Y[0] (verified) ----------------
__global__ void k_T(const float* __restrict__ Om1, const float* __restrict__ U) {
    __shared__ float sOm[MR * 64];
    int t = threadIdx.x;
    for (int i = t; i < MR * 64; i += 128) sOm[i] = Om1[i];
    __syncthreads();
    int kc = blockIdx.x;
    __half* dst = &g_Yp[0][(size_t)kc * 1024];
    for (int e = t; e < 512; e += 128) {
        int m = e >> 4, kk = e & 15;
        int k = kc * 16 + kk;
        float v = 0.f;
        #pragma unroll
        for (int p = 0; p < 64; p++) v += sOm[m * 64 + p] * U[(size_t)p * NCOLS + k];
        __half h, l; hilo(v, h, l);
        dst[m * 16 + kk] = h;
        dst[512 + m * 16 + kk] = l;
    }
}

// ---------------- 4. Fused Picard pass: BN=128, 256 thr, 2 CTA/SM ------------
__global__ void __launch_bounds__(256, 2)
k_iter(const int* __restrict__ fw, float* __restrict__ out,
       int it, int src, int writeB, int useB) {
    extern __shared__ __align__(16) unsigned char sBuf[];   // STAGES*STGB dynamic
    __shared__ int sLast;

    const int t = threadIdx.x;
    const int nb = blockIdx.x % NB;
    const int sp = blockIdx.x / NB;
    const int w = t >> 5, lane = t & 31;     // 8 warps, each owns 16 A-cols

    const int fwv = *fw;
    if (it > fwv) return;

    const int kbeg = (sp * KCH) / KSPLIT;
    const int kend = ((sp + 1) * KCH) / KSPLIT;

    const __half* Asrc = &g_Apk[(size_t)nb * KCH * 4096];
    const __half* Ysrc = g_Yp[src];
    const uint32_t base = (uint32_t)__cvta_generic_to_shared(sBuf);

    // cp.async mapping: A 512 granules -> 2/thread; Y 128 -> threads<128
    const int g0 = t, g1 = t + 256;
    const int a0H = g0 >> 8, a0C = (g0 & 255) >> 1, a0S = g0 & 1;
    const int a1H = g1 >> 8, a1C = (g1 & 255) >> 1, a1S = g1 & 1;
    const uint32_t dA0 = ((a0H * 128 + a0C) * 24 + a0S * 8) * 2;
    const uint32_t dA1 = ((a1H * 128 + a1C) * 24 + a1S * 8) * 2;
    const int sA0 = a0H * 2048 + a0C * 16 + a0S * 8;
    const int sA1 = a1H * 2048 + a1C * 16 + a1S * 8;
    const int yH = (t >> 6) & 1, yI = t & 63;
    const int yM2 = yI >> 1, yS = yI & 1;
    const uint32_t dY = ((yH * 32 + yM2) * 24 + yS * 8) * 2;
    const int     sY = yH * 512 + yM2 * 16 + yS * 8;
    const bool hasY = (t < 128);

    // ldmatrix per-lane byte offsets
    const int tl = lane >> 3, rl = lane & 7;
    const int aRow = w * 16 + ((tl & 1) << 3) + rl;
    const int aKo  = (tl >> 1) << 3;
    const uint32_t offAhi = (uint32_t)((aRow)       * 24 + aKo) * 2;
    const uint32_t offAlo = (uint32_t)((128 + aRow) * 24 + aKo) * 2;
    const int yM  = ((tl >> 1) << 3) + rl;
    const int yKo = (tl & 1) << 3;
    const uint32_t offYh0 = (uint32_t)((yM)           * 24 + yKo) * 2;
    const uint32_t offYh1 = (uint32_t)((yM + 16)      * 24 + yKo) * 2;
    const uint32_t offYl0 = (uint32_t)((32 + yM)      * 24 + yKo) * 2;
    const uint32_t offYl1 = (uint32_t)((32 + yM + 16) * 24 + yKo) * 2;

    auto issue = [&](int kc2) {
        int buf = (kc2 - kbeg) % STAGES;
        uint32_t ab = base + buf * STGB;
        const __half* ac = Asrc + (size_t)kc2 * 4096;
        cpa16(ab + dA0, ac + sA0);
        cpa16(ab + dA1, ac + sA1);
        if (hasY) cpa16(ab + 12288 + dY, Ysrc + (size_t)kc2 * 1024 + sY);
    };

    // prologue
    #pragma unroll
    for (int p = 0; p < STAGES - 1; p++) {
        issue(kbeg + p);
        asm volatile("cp.async.commit_group;");
    }

    float Cm[4][4], Cs[4][4];
    #pragma unroll
    for (int j = 0; j < 4; j++)
        #pragma unroll
        for (int q = 0; q < 4; q++) { Cm[j][q] = 0.f; Cs[j][q] = 0.f; }

    for (int c = kbeg; c < kend; c++) {
        asm volatile("cp.async.wait_group %0;" :: "n"(STAGES - 2));
        __syncthreads();
        int nkc = c + STAGES - 1;
        if (nkc < kend) issue(nkc);
        asm volatile("cp.async.commit_group;");

        int buf = (c - kbeg) % STAGES;
        uint32_t ab = base + buf * STGB;
        uint32_t yb = ab + 12288;

        uint32_t Ah[4], Al[4], Bh0[4], Bh1[4], Bl0[4], Bl1[4];
        ldm4(Ah,  ab + offAhi);
        ldm4(Al,  ab + offAlo);
        ldm4(Bh0, yb + offYh0);
        ldm4(Bh1, yb + offYh1);
        ldm4(Bl0, yb + offYl0);
        ldm4(Bl1, yb + offYl1);

        mma_(Cm[0], Ah, Bh0[0], Bh0[1]);
        mma_(Cm[1], Ah, Bh0[2], Bh0[3]);
        mma_(Cm[2], Ah, Bh1[0], Bh1[1]);
        mma_(Cm[3], Ah, Bh1[2], Bh1[3]);

        mma_(Cs[0], Ah, Bl0[0], Bl0[1]);
        mma_(Cs[1], Ah, Bl0[2], Bl0[3]);
        mma_(Cs[2], Ah, Bl1[0], Bl1[1]);
        mma_(Cs[3], Ah, Bl1[2], Bl1[3]);

        mma_(Cs[0], Al, Bh0[0], Bh0[1]);
        mma_(Cs[1], Al, Bh0[2], Bh0[3]);
        mma_(Cs[2], Al, Bh1[0], Bh1[1]);
        mma_(Cs[3], Al, Bh1[2], Bh1[3]);
    }
    asm volatile("cp.async.wait_group 0;");
    __syncthreads();

    // scatter C frags -> sZ[c][m]  (overlay on drained pipeline smem)
    float (*sZ)[33] = (float (*)[33])sBuf;
    {
        const int g = lane >> 2, i2 = (lane & 3) << 1;
        const int cc = w * 16 + g;
        #pragma unroll
        for (int j = 0; j < 4; j++) {
            int m = j * 8 + i2;
            sZ[cc][m]         = Cm[j][0] + Cs[j][0] * INV2048;
            sZ[cc][m + 1]     = Cm[j][1] + Cs[j][1] * INV2048;
            sZ[cc + 8][m]     = Cm[j][2] + Cs[j][2] * INV2048;
            sZ[cc + 8][m + 1] = Cm[j][3] + Cs[j][3] * INV2048;
        }
    }
    __syncthreads();

    // store partial Z (coalesced float4, 16 floats per thread)
    {
        float* gp = &g_Zp[((size_t)(sp * NB + nb)) * 4096];
        #pragma unroll
        for (int q = 0; q < 4; q++) {
            int idx = t * 16 + q * 4;
            int cc = idx >> 5, m = idx & 31;
            float4 v = make_float4(sZ[cc][m], sZ[cc][m + 1], sZ[cc][m + 2], sZ[cc][m + 3]);
            *reinterpret_cast<float4*>(gp + idx) = v;
        }
    }
    __threadfence();
    __syncthreads();
    if (t == 0) {
        int old = atomicAdd(&g_cnt[nb], 1);
        sLast = (old == KSPLIT - 1);
    }
    __syncthreads();
    if (!sLast) return;

    // ---- ticket CTA: reduce partials + epilogue ----
    float* sWp = (float*)(sBuf + 128 * 33 * 4);   // after sZ, within drained smem
    for (int i = t; i < MR * MR; i += 256) sWp[i] = g_Wp[i];

    const int col = t >> 1, r0 = (t & 1) << 4;    // 2 threads/col, 16 rows each
    const int gcol = nb * BN + col;
    float z[16];
    #pragma unroll
    for (int q = 0; q < 4; q++) {
        float4 acc = make_float4(0.f, 0.f, 0.f, 0.f);
        #pragma unroll
        for (int s2 = 0; s2 < KSPLIT; s2++) {
            const float4* p = reinterpret_cast<const float4*>(
                &g_Zp[((size_t)(s2 * NB + nb)) * 4096 + col * 32 + r0 + q * 4]);
            float4 v = __ldcg(p);
            acc.x += v.x; acc.y += v.y; acc.z += v.z; acc.w += v.w;
        }
        z[q * 4 + 0] = acc.x; z[q * 4 + 1] = acc.y;
        z[q * 4 + 2] = acc.z; z[q * 4 + 3] = acc.w;
    }

    float* Bp = &g_B[(nb * BN + col) * MR];
    const bool writeOut = (it == fwv);
    const bool writeY   = (it < fwv);

    #pragma unroll
    for (int r = 0; r < 16; r++) {
        int rr = r0 + r;
        float zz = z[r];
        if (useB)   zz += Bp[rr];
        if (writeB) Bp[rr] = zz;
        float xv = fmaxf(zz, 0.0f);
        if (writeOut && gcol < NCOLS) out[(size_t)rr * NCOLS + gcol] = xv;
        sZ[col][rr] = xv;
    }
    __syncthreads();

    if (writeY) {
        int kc = gcol >> 4, kk = gcol & 15;
        __half* Yd = g_Yp[src ^ 1] + (size_t)kc * 1024;
        #pragma unroll
        for (int r = 0; r < 16; r++) {
            int rr = r0 + r;
            float y = 0.f;
            #pragma unroll
            for (int j = 0; j < MR; j++) y += sWp[rr * MR + j] * sZ[col][j];
            __half h, l; hilo(y, h, l);
            Yd[rr * 16 + kk] = h;
            Yd[512 + rr * 16 + kk] = l;
        }
    }
    if (t == 0) g_cnt[nb] = 0;   // reset for next pass / replay
}

// ---------------- launch ----------------
// Inputs: W, Omega_1, Omega_2, X_0, A, U, fw_mitr
extern "C" void kernel_launch(void* const* d_in, const int* in_sizes, int n_in,
                              void* d_out, int out_size) {
    const float* W   = (const float*)d_in[0];
    const float* Om1 = (const float*)d_in[1];
    const float* A   = (const float*)d_in[4];
    const float* U   = (const float*)d_in[5];
    const int*   fw  = (const int*)  d_in[6];
    float*       out = (float*)d_out;

    static int attrDone = 0;
    if (!attrDone) {
        cudaFuncSetAttribute(k_iter, cudaFuncAttributeMaxDynamicSharedMemorySize, SMEMSZ);
        attrDone = 1;
    }

    k_project<<<1, 32>>>(W);
    k_convA<<<NB * KCH, 128>>>(A);
    k_T<<<KCH, 128>>>(Om1, U);

    // it = 1: Z = T@A = b ; B := Z ; X1 = relu(b) ; Y1 = Wp@X1
    k_iter<<<NB * KSPLIT, 256, SMEMSZ>>>(fw, out, 1, 0, 1, 0);
    // it = 2..30
    for (int it = 2; it <= 30; it++)
        k_iter<<<NB * KSPLIT, 256, SMEMSZ>>>(fw, out, it, (it - 1) & 1, 0, 1);
}

// round 14
// speedup vs baseline: 1.3615x; 1.0143x over previous
#include <cuda_runtime.h>
#include <cuda_fp16.h>
#include <cstdint>

#define MR     32
#define NCOLS  10000
#define KDIM   10000
#define NB     79         // column blocks of 128 (79*128 = 10112 padded)
#define BN     128
#define KCH    625        // k-chunks of 16
#define NPCH   632        // padded chunk count for Y buffers
#define NSTG   5          // per-warp A pipeline stages
#define YGRP   8          // chunks per Y super-group
#define KSPLIT 16
#define AWSTG  1536       // bytes per warp A stage (32 rows x 48B)
#define ABYTES (8 * NSTG * AWSTG)            // 61440
#define YCHNK  3072       // bytes per Y chunk in smem (64 rows x 48B)
#define YBYTES (2 * YGRP * YCHNK)            // 49152
#define SMEMSZ (ABYTES + YBYTES)             // 110592
#define INV2048 (1.0f/2048.0f)

// ---------------- device scratch (allocation-free) ----------------
__device__ __align__(16) __half g_Apk[(size_t)NB * KCH * 4096];   // ~404 MB
__device__ __align__(16) __half g_Yp[2][(size_t)NPCH * 1024];
__device__ __align__(16) float  g_Zp[(size_t)KSPLIT * NB * 4096];
__device__ float  g_B[NB * BN * MR];
__device__ float  g_Wp[MR * MR];
__device__ int    g_cnt[NB];                                      // zero-init; self-resetting

// ---------------- helpers ----------------
__device__ __forceinline__ void cpa16(uint32_t d, const void* s) {
    asm volatile("cp.async.cg.shared.global [%0], [%1], 16;" :: "r"(d), "l"(s));
}
__device__ __forceinline__ void ldm4(uint32_t* r, uint32_t a) {
    asm volatile("ldmatrix.sync.aligned.m8n8.x4.shared.b16 {%0,%1,%2,%3}, [%4];"
        : "=r"(r[0]), "=r"(r[1]), "=r"(r[2]), "=r"(r[3]) : "r"(a));
}
__device__ __forceinline__ void mma_(float* c, const uint32_t* a, uint32_t b0, uint32_t b1) {
    asm volatile("mma.sync.aligned.m16n8k16.row.col.f32.f16.f16.f32 "
        "{%0,%1,%2,%3}, {%4,%5,%6,%7}, {%8,%9}, {%0,%1,%2,%3};"
        : "+f"(c[0]), "+f"(c[1]), "+f"(c[2]), "+f"(c[3])
        : "r"(a[0]), "r"(a[1]), "r"(a[2]), "r"(a[3]), "r"(b0), "r"(b1));
}
__device__ __forceinline__ void hilo(float v, __half& h, __half& l) {
    h = __float2half_rn(v);
    l = __float2half_rn((v - __half2float(h)) * 2048.0f);
}

// ---------------- 1. W projection (verified) ----------------
__global__ void k_project(const float* __restrict__ W) {
    int r = threadIdx.x;
    if (r >= MR) return;
    float a[32], u[32];
    float s = 0.0f;
    for (int i = 0; i < 32; i++) { a[i] = W[r * 32 + i]; u[i] = fabsf(a[i]); s += u[i]; }
    const float v = 0.99f;
    if (s > v) {
        for (int i = 1; i < 32; i++) {
            float key = u[i]; int j = i - 1;
            while (j >= 0 && u[j] < key) { u[j + 1] = u[j]; j--; }
            u[j + 1] = key;
        }
        float cs = 0.0f; int rho = 0;
        for (int i = 0; i < 32; i++) {
            cs += u[i];
            if (u[i] - (cs - v) / (float)(i + 1) > 0.0f) rho++;
        }
        float cs2 = 0.0f;
        for (int i = 0; i < rho; i++) cs2 += u[i];
        float theta = (cs2 - v) / (float)rho;
        for (int i = 0; i < 32; i++) {
            float m = fmaxf(fabsf(a[i]) - theta, 0.0f);
            a[i] = (a[i] > 0.0f) ? m : ((a[i] < 0.0f) ? -m : 0.0f);
        }
    }
    for (int i = 0; i < 32; i++) g_Wp[r * 32 + i] = a[i];
}

// ---------------- 2. Convert A -> blocked fp16 hi/lo, BN=128 (verified) ------
__global__ void k_convA(const float* __restrict__ A) {
    __shared__ __align__(16) float sA[16][132];
    int b  = blockIdx.x;               // nb*KCH + kc
    int nb = b / KCH, kc = b % KCH;
    int t  = threadIdx.x;
    int k0 = kc * 16, c0 = nb * BN;
    for (int e = t; e < 2048; e += 128) {
        int kk = e >> 7, c = e & 127;
        int gc = c0 + c;
        float v0 = 0.0f;
        if (gc < NCOLS) v0 = A[(size_t)(k0 + kk) * NCOLS + gc];
        sA[kk][c] = v0;
    }
    __syncthreads();
    __half* dst = &g_Apk[(size_t)b * 4096];
    for (int e = t; e < 2048; e += 128) {
        int c = e >> 4, kk = e & 15;
        __half h, l; hilo(sA[kk][c], h, l);
        dst[e] = h;
        dst[2048 + e] = l;
    }
}

// ---------------- 3. T = Omega_1 @ U -> Y[0] (verified) ----------------
__global__ void k_T(const float* __restrict__ Om1, const float* __restrict__ U) {
    __shared__ float sOm[MR * 64];
    int t = threadIdx.x;
    for (int i = t; i < MR * 64; i += 128) sOm[i] = Om1[i];
    __syncthreads();
    int kc = blockIdx.x;
    __half* dst = &g_Yp[0][(size_t)kc * 1024];
    for (int e = t; e < 512; e += 128) {
        int m = e >> 4, kk = e & 15;
        int k = kc * 16 + kk;
        float v = 0.f;
        #pragma unroll
        for (int p = 0; p < 64; p++) v += sOm[m * 64 + p] * U[(size_t)p * NCOLS + k];
        __half h, l; hilo(v, h, l);
        dst[m * 16 + kk] = h;
        dst[512 + m * 16 + kk] = l;
    }
}

// ---------------- 4. Picard pass: warp-private A pipes, barrier-free mainloop -
__global__ void __launch_bounds__(256, 2)
k_iter(const int* __restrict__ fw, float* __restrict__ out,
       int it, int src, int writeB, int useB) {
    extern __shared__ __align__(16) unsigned char sBuf[];   // SMEMSZ dynamic
    __shared__ int sLast;

    const int t = threadIdx.x;
    const int nb = blockIdx.x % NB;
    const int sp = blockIdx.x / NB;
    const int w = t >> 5, lane = t & 31;   // 8 warps, warp owns cols w*16..+15

    const int fwv = *fw;
    if (it > fwv) return;

    const int kbeg = (sp * KCH) / KSPLIT;
    const int kend = ((sp + 1) * KCH) / KSPLIT;
    const int len  = kend - kbeg;

    const __half* Asrc = &g_Apk[(size_t)nb * KCH * 4096];
    const __half* Ysrc = g_Yp[src];
    const uint32_t base = (uint32_t)__cvta_generic_to_shared(sBuf);
    const uint32_t yBase = base + ABYTES;

    // per-lane A cp.async dst/src offsets (hi granule L, lo granule L)
    const uint32_t dHi = (uint32_t)((lane >> 1) * 48 + (lane & 1) * 16);
    const int      sHi = w * 256 + lane * 8;          // halves
    // warp stage base
    const uint32_t wStage0 = base + (uint32_t)(w * NSTG) * AWSTG;

    // ldmatrix per-lane byte offsets
    const int tl = lane >> 3, rl = lane & 7;
    const int aRow = ((tl & 1) << 3) + rl;            // 0..15 within slice
    const int aKo  = (tl >> 1) << 3;
    const uint32_t offAhi = (uint32_t)((aRow)      * 24 + aKo) * 2;
    const uint32_t offAlo = (uint32_t)((16 + aRow) * 24 + aKo) * 2;
    const int yM  = ((tl >> 1) << 3) + rl;
    const int yKo = (tl & 1) << 3;
    const uint32_t offYh0 = (uint32_t)((yM)           * 24 + yKo) * 2;
    const uint32_t offYh1 = (uint32_t)((yM + 16)      * 24 + yKo) * 2;
    const uint32_t offYl0 = (uint32_t)((32 + yM)      * 24 + yKo) * 2;
    const uint32_t offYl1 = (uint32_t)((32 + yM + 16) * 24 + yKo) * 2;

    auto issueA = [&](int i) {        // local chunk index i
        uint32_t ab = wStage0 + (uint32_t)(i % NSTG) * AWSTG;
        const __half* ac = Asrc + (size_t)(kbeg + i) * 4096;
        cpa16(ab + dHi,       ac + sHi);
        cpa16(ab + 768 + dHi, ac + 2048 + sHi);
    };
    // cooperative Y super-group load: 4 granules per thread
    auto issueY = [&](int g) {        // group index
        int c0 = g * YGRP;
        uint32_t yb = yBase + (uint32_t)(g & 1) * (YGRP * YCHNK);
        #pragma unroll
        for (int q = 0; q < 4; q++) {
            int gg = t + 256 * q;               // 0..1023
            int j  = gg >> 7, r = gg & 127;
            if (c0 + j < len)
                cpa16(yb + (uint32_t)(j * YCHNK + (r >> 1) * 48 + (r & 1) * 16),
                      Ysrc + (size_t)(kbeg + c0 + j) * 1024 + r * 8);
        }
    };

    // prologue: G0 = Y(0)+Y(1)+A(0); G1..G(NSTG-2) = A(1..NSTG-2)
    issueY(0);
    issueY(1);
    issueA(0);
    asm volatile("cp.async.commit_group;");
    #pragma unroll
    for (int p = 1; p < NSTG - 1; p++) {
        if (p < len) issueA(p);
        asm volatile("cp.async.commit_group;");
    }
    asm volatile("cp.async.wait_group %0;" :: "n"(NSTG - 2));
    __syncthreads();                       // Y group 0/1 visible CTA-wide

    float Cm[4][4], Cs[4][4];
    #pragma unroll
    for (int j = 0; j < 4; j++)
        #pragma unroll
        for (int q = 0; q < 4; q++) { Cm[j][q] = 0.f; Cs[j][q] = 0.f; }

    for (int i = 0; i < len; i++) {
        if ((i & (YGRP - 1)) == 0 && i > 0) {
            __syncthreads();               // all warps done with Y buf being replaced
            issueY((i >> 3) + 1);          // guarded internally
        }
        if (i + NSTG - 1 < len) issueA(i + NSTG - 1);
        asm volatile("cp.async.commit_group;");
        asm volatile("cp.async.wait_group %0;" :: "n"(NSTG - 2));
        __syncwarp();

        uint32_t ab = wStage0 + (uint32_t)(i % NSTG) * AWSTG;
        uint32_t yb = yBase + (uint32_t)((i >> 3) & 1) * (YGRP * YCHNK)
                            + (uint32_t)(i & (YGRP - 1)) * YCHNK;

        uint32_t Ah[4], Al[4], Bh0[4], Bh1[4], Bl0[4], Bl1[4];
        ldm4(Ah,  ab + offAhi);
        ldm4(Al,  ab + offAlo);
        ldm4(Bh0, yb + offYh0);
        ldm4(Bh1, yb + offYh1);
        ldm4(Bl0, yb + offYl0);
        ldm4(Bl1, yb + offYl1);

        mma_(Cm[0], Ah, Bh0[0], Bh0[1]);
        mma_(Cm[1], Ah, Bh0[2], Bh0[3]);
        mma_(Cm[2], Ah, Bh1[0], Bh1[1]);
        mma_(Cm[3], Ah, Bh1[2], Bh1[3]);

        mma_(Cs[0], Ah, Bl0[0], Bl0[1]);
        mma_(Cs[1], Ah, Bl0[2], Bl0[3]);
        mma_(Cs[2], Ah, Bl1[0], Bl1[1]);
        mma_(Cs[3], Ah, Bl1[2], Bl1[3]);

        mma_(Cs[0], Al, Bh0[0], Bh0[1]);
        mma_(Cs[1], Al, Bh0[2], Bh0[3]);
        mma_(Cs[2], Al, Bh1[0], Bh1[1]);
        mma_(Cs[3], Al, Bh1[2], Bh1[3]);
    }
    asm volatile("cp.async.wait_group 0;");
    __syncthreads();

    // scatter C frags -> sZ[c][m]  (overlay on drained A-pipeline smem)
    float (*sZ)[33] = (float (*)[33])sBuf;
    {
        const int g = lane >> 2, i2 = (lane & 3) << 1;
        const int cc = w * 16 + g;
        #pragma unroll
        for (int j = 0; j < 4; j++) {
            int m = j * 8 + i2;
            sZ[cc][m]         = Cm[j][0] + Cs[j][0] * INV2048;
            sZ[cc][m + 1]     = Cm[j][1] + Cs[j][1] * INV2048;
            sZ[cc + 8][m]     = Cm[j][2] + Cs[j][2] * INV2048;
            sZ[cc + 8][m + 1] = Cm[j][3] + Cs[j][3] * INV2048;
        }
    }
    __syncthreads();

    // store partial Z (coalesced float4, 16 floats per thread)
    {
        float* gp = &g_Zp[((size_t)(sp * NB + nb)) * 4096];
        #pragma unroll
        for (int q = 0; q < 4; q++) {
            int idx = t * 16 + q * 4;
            int cc = idx >> 5, m = idx & 31;
            float4 v = make_float4(sZ[cc][m], sZ[cc][m + 1], sZ[cc][m + 2], sZ[cc][m + 3]);
            *reinterpret_cast<float4*>(gp + idx) = v;
        }
    }
    __threadfence();
    __syncthreads();
    if (t == 0) {
        int old = atomicAdd(&g_cnt[nb], 1);
        sLast = (old == KSPLIT - 1);
    }
    __syncthreads();
    if (!sLast) return;

    // ---- ticket CTA: reduce partials + epilogue ----
    float* sWp = (float*)(sBuf + 128 * 33 * 4);
    for (int i = t; i < MR * MR; i += 256) sWp[i] = g_Wp[i];

    const int col = t >> 1, r0 = (t & 1) << 4;
    const int gcol = nb * BN + col;
    float z[16];
    #pragma unroll
    for (int q = 0; q < 4; q++) {
        float4 acc = make_float4(0.f, 0.f, 0.f, 0.f);
        #pragma unroll
        for (int s2 = 0; s2 < KSPLIT; s2++) {
            const float4* p = reinterpret_cast<const float4*>(
                &g_Zp[((size_t)(s2 * NB + nb)) * 4096 + col * 32 + r0 + q * 4]);
            float4 v = __ldcg(p);
            acc.x += v.x; acc.y += v.y; acc.z += v.z; acc.w += v.w;
        }
        z[q * 4 + 0] = acc.x; z[q * 4 + 1] = acc.y;
        z[q * 4 + 2] = acc.z; z[q * 4 + 3] = acc.w;
    }

    float* Bp = &g_B[(nb * BN + col) * MR];
    const bool writeOut = (it == fwv);
    const bool writeY   = (it < fwv);

    #pragma unroll
    for (int r = 0; r < 16; r++) {
        int rr = r0 + r;
        float zz = z[r];
        if (useB)   zz += Bp[rr];
        if (writeB) Bp[rr] = zz;
        float xv = fmaxf(zz, 0.0f);
        if (writeOut && gcol < NCOLS) out[(size_t)rr * NCOLS + gcol] = xv;
        sZ[col][rr] = xv;
    }
    __syncthreads();

    if (writeY) {
        int kc = gcol >> 4, kk = gcol & 15;
        __half* Yd = g_Yp[src ^ 1] + (size_t)kc * 1024;
        #pragma unroll
        for (int r = 0; r < 16; r++) {
            int rr = r0 + r;
            float y = 0.f;
            #pragma unroll
            for (int j = 0; j < MR; j++) y += sWp[rr * MR + j] * sZ[col][j];
            __half h, l; hilo(y, h, l);
            Yd[rr * 16 + kk] = h;
            Yd[512 + rr * 16 + kk] = l;
        }
    }
    if (t == 0) g_cnt[nb] = 0;   // reset for next pass / replay
}

// ---------------- launch ----------------
// Inputs: W, Omega_1, Omega_2, X_0, A, U, fw_mitr
extern "C" void kernel_launch(void* const* d_in, const int* in_sizes, int n_in,
                              void* d_out, int out_size) {
    const float* W   = (const float*)d_in[0];
    const float* Om1 = (const float*)d_in[1];
    const float* A   = (const float*)d_in[4];
    const float* U   = (const float*)d_in[5];
    const int*   fw  = (const int*)  d_in[6];
    float*       out = (float*)d_out;

    static int attrDone = 0;
    if (!attrDone) {
        cudaFuncSetAttribute(k_iter, cudaFuncAttributeMaxDynamicSharedMemorySize, SMEMSZ);
        attrDone = 1;
    }

    k_project<<<1, 32>>>(W);
    k_convA<<<NB * KCH, 128>>>(A);
    k_T<<<KCH, 128>>>(Om1, U);

    // it = 1: Z = T@A = b ; B := Z ; X1 = relu(b) ; Y1 = Wp@X1
    k_iter<<<NB * KSPLIT, 256, SMEMSZ>>>(fw, out, 1, 0, 1, 0);
    // it = 2..30
    for (int it = 2; it <= 30; it++)
        k_iter<<<NB * KSPLIT, 256, SMEMSZ>>>(fw, out, it, (it - 1) & 1, 0, 1);
}

// round 16
// speedup vs baseline: 1.4091x; 1.0349x over previous
#include <cuda_runtime.h>
#include <cuda_fp16.h>
#include <cstdint>

#define MR     32
#define NCOLS  10000
#define NB     79         // column blocks of 128 (79*128 = 10112 padded)
#define BN     128
#define KCH    625        // k-chunks of 16
#define NPCH   632        // padded chunk count for Y buffers
#define KSPLIT 16
#define GROUP  5
#define SLOTS  10
#define CHB    10240      // chunk bytes in smem: A 8192 + Y 2048
#define SMEMSZ (SLOTS * CHB)       // 102400
#define INV2048 (1.0f/2048.0f)

// ---------------- device scratch (allocation-free) ----------------
// per (nb,kc) chunk: 2048 hi halves [c][kk], then 2048 lo.  8 KB contiguous.
__device__ __align__(16) __half g_Apk[(size_t)NB * KCH * 4096];   // ~404 MB
// per kc: 512 hi halves [m][kk], then 512 lo.  2 KB contiguous.
__device__ __align__(16) __half g_Yp[2][(size_t)NPCH * 1024];
__device__ __align__(16) float  g_Zp[(size_t)KSPLIT * NB * 4096];
__device__ float  g_B[NB * BN * MR];
__device__ float  g_Wp[MR * MR];
__device__ int    g_cnt[NB];                                      // zero-init; self-resetting

// ---------------- helpers ----------------
__device__ __forceinline__ void ldm4(uint32_t* r, uint32_t a) {
    asm volatile("ldmatrix.sync.aligned.m8n8.x4.shared.b16 {%0,%1,%2,%3}, [%4];"
        : "=r"(r[0]), "=r"(r[1]), "=r"(r[2]), "=r"(r[3]) : "r"(a));
}
__device__ __forceinline__ void mma_(float* c, const uint32_t* a, uint32_t b0, uint32_t b1) {
    asm volatile("mma.sync.aligned.m16n8k16.row.col.f32.f16.f16.f32 "
        "{%0,%1,%2,%3}, {%4,%5,%6,%7}, {%8,%9}, {%0,%1,%2,%3};"
        : "+f"(c[0]), "+f"(c[1]), "+f"(c[2]), "+f"(c[3])
        : "r"(a[0]), "r"(a[1]), "r"(a[2]), "r"(a[3]), "r"(b0), "r"(b1));
}
__device__ __forceinline__ void hilo(float v, __half& h, __half& l) {
    h = __float2half_rn(v);
    l = __float2half_rn((v - __half2float(h)) * 2048.0f);
}
__device__ __forceinline__ void bulk_ld(uint32_t dst, const void* src, uint32_t bytes, uint32_t mbar) {
    asm volatile(
        "cp.async.bulk.shared::cluster.global.mbarrier::complete_tx::bytes [%0], [%1], %2, [%3];"
        :: "r"(dst), "l"(src), "r"(bytes), "r"(mbar) : "memory");
}
__device__ __forceinline__ void mbar_wait(uint32_t mbar, uint32_t parity) {
    uint32_t done;
    asm volatile(
        "{\n\t.reg .pred p;\n\t"
        "mbarrier.try_wait.parity.acquire.cta.shared::cta.b64 p, [%1], %2;\n\t"
        "selp.b32 %0, 1, 0, p;\n\t}"
        : "=r"(done) : "r"(mbar), "r"(parity) : "memory");
    if (!done) {
        asm volatile(
            "{\n\t.reg .pred P1;\n\t"
            "W_%=:\n\t"
            "mbarrier.try_wait.parity.acquire.cta.shared::cta.b64 P1, [%0], %1, 0x989680;\n\t"
            "@P1 bra.uni D_%=;\n\t"
            "bra.uni W_%=;\n\t"
            "D_%=:\n\t}"
            :: "r"(mbar), "r"(parity) : "memory");
    }
}

// ---------------- 1. W projection (verified) ----------------
__global__ void k_project(const float* __restrict__ W) {
    int r = threadIdx.x;
    if (r >= MR) return;
    float a[32], u[32];
    float s = 0.0f;
    for (int i = 0; i < 32; i++) { a[i] = W[r * 32 + i]; u[i] = fabsf(a[i]); s += u[i]; }
    const float v = 0.99f;
    if (s > v) {
        for (int i = 1; i < 32; i++) {
            float key = u[i]; int j = i - 1;
            while (j >= 0 && u[j] < key) { u[j + 1] = u[j]; j--; }
            u[j + 1] = key;
        }
        float cs = 0.0f; int rho = 0;
        for (int i = 0; i < 32; i++) {
            cs += u[i];
            if (u[i] - (cs - v) / (float)(i + 1) > 0.0f) rho++;
        }
        float cs2 = 0.0f;
        for (int i = 0; i < rho; i++) cs2 += u[i];
        float theta = (cs2 - v) / (float)rho;
        for (int i = 0; i < 32; i++) {
            float m = fmaxf(fabsf(a[i]) - theta, 0.0f);
            a[i] = (a[i] > 0.0f) ? m : ((a[i] < 0.0f) ? -m : 0.0f);
        }
    }
    for (int i = 0; i < 32; i++) g_Wp[r * 32 + i] = a[i];
}

// ---------------- 2. Convert A -> packed blocked fp16 hi/lo (verified R13) ----
__global__ void k_convA(const float* __restrict__ A) {
    __shared__ __align__(16) float sA[16][132];
    int b  = blockIdx.x;               // nb*KCH + kc
    int nb = b / KCH, kc = b % KCH;
    int t  = threadIdx.x;
    int k0 = kc * 16, c0 = nb * BN;
    for (int e = t; e < 2048; e += 128) {
        int kk = e >> 7, c = e & 127;
        int gc = c0 + c;
        float v0 = 0.0f;
        if (gc < NCOLS) v0 = A[(size_t)(k0 + kk) * NCOLS + gc];
        sA[kk][c] = v0;
    }
    __syncthreads();
    __half* dst = &g_Apk[(size_t)b * 4096];
    for (int e = t; e < 2048; e += 128) {
        int c = e >> 4, kk = e & 15;
        __half h, l; hilo(sA[kk][c], h, l);
        dst[e] = h;
        dst[2048 + e] = l;
    }
}

// ---------------- 3. T = Omega_1 @ U -> Y[0] packed (verified) ----------------
__global__ void k_T(const float* __restrict__ Om1, const float* __restrict__ U) {
    __shared__ float sOm[MR * 64];
    int t = threadIdx.x;
    for (int i = t; i < MR * 64; i += 128) sOm[i] = Om1[i];
    __syncthreads();
    int kc = blockIdx.x;
    __half* dst = &g_Yp[0][(size_t)kc * 1024];
    for (int e = t; e < 512; e += 128) {
        int m = e >> 4, kk = e & 15;
        int k = kc * 16 + kk;
        float v = 0.f;
        #pragma unroll
        for (int p = 0; p < 64; p++) v += sOm[m * 64 + p] * U[(size_t)p * NCOLS + k];
        __half h, l; hilo(v, h, l);
        dst[m * 16 + kk] = h;
        dst[512 + m * 16 + kk] = l;
    }
}

// ---------------- 4. Fused Picard pass: bulk-copy pipeline -------------------
__global__ void __launch_bounds__(256, 2)
k_iter(const int* __restrict__ fw, float* __restrict__ out,
       int it, int src, int writeB, int useB) {
    extern __shared__ __align__(1024) unsigned char sBuf[];   // SMEMSZ dynamic
    __shared__ __align__(8) unsigned long long sFull[SLOTS];
    __shared__ int sLast;

    const int t = threadIdx.x;
    const int nb = blockIdx.x % NB;
    const int sp = blockIdx.x / NB;
    const int w = t >> 5, lane = t & 31;     // 8 warps, warp owns A-cols w*16..+15

    const int fwv = *fw;
    if (it > fwv) return;

    const int kbeg = (sp * KCH) / KSPLIT;
    const int kend = ((sp + 1) * KCH) / KSPLIT;
    const int len  = kend - kbeg;

    const __half* Asrc = &g_Apk[(size_t)nb * KCH * 4096];
    const __half* Ysrc = g_Yp[src];
    const uint32_t base = (uint32_t)__cvta_generic_to_shared(sBuf);
    const uint32_t mb0  = (uint32_t)__cvta_generic_to_shared(&sFull[0]);

    if (t == 0) {
        #pragma unroll
        for (int s = 0; s < SLOTS; s++)
            asm volatile("mbarrier.init.shared.b64 [%0], %1;"
                :: "r"(mb0 + s * 8), "r"(1u) : "memory");
    }
    __syncthreads();

    auto issueChunk = [&](int q) {           // local chunk index
        if (q >= len) return;
        int s = q % SLOTS;
        uint32_t sb = base + (uint32_t)s * CHB;
        uint32_t mb = mb0 + s * 8;
        asm volatile("mbarrier.arrive.expect_tx.shared.b64 _, [%0], %1;"
            :: "r"(mb), "r"((uint32_t)CHB) : "memory");
        bulk_ld(sb,        Asrc + (size_t)(kbeg + q) * 4096, 8192, mb);
        bulk_ld(sb + 8192, Ysrc + (size_t)(kbeg + q) * 1024, 2048, mb);
    };

    if (t == 0)
        for (int q = 0; q < 2 * GROUP; q++) issueChunk(q);

    // ldmatrix per-lane byte offsets (packed rows, 32 B stride)
    const int tl = lane >> 3, rl = lane & 7;
    const int aRow = w * 16 + ((tl & 1) << 3) + rl;
    const uint32_t offAhi = (uint32_t)(aRow * 32 + ((tl >> 1) & 1) * 16);
    const uint32_t offAlo = 4096u + offAhi;
    const int yM = ((tl >> 1) << 3) + rl;
    const uint32_t offYh0 = 8192u + (uint32_t)(yM * 32 + (tl & 1) * 16);
    const uint32_t offYh1 = offYh0 + 512u;
    const uint32_t offYl0 = offYh0 + 1024u;
    const uint32_t offYl1 = offYl0 + 512u;

    float Cm[4][4], Cs[4][4];
    #pragma unroll
    for (int j = 0; j < 4; j++)
        #pragma unroll
        for (int q = 0; q < 4; q++) { Cm[j][q] = 0.f; Cs[j][q] = 0.f; }

    for (int j = 0; j < len; j++) {
        if (j > 0 && (j % GROUP) == 0) {
            __syncthreads();                 // group j/GROUP-1's slots fully consumed
            if (t == 0)
                for (int q = j + GROUP; q < j + 2 * GROUP; q++) issueChunk(q);
        }
        int s = j % SLOTS;
        mbar_wait(mb0 + s * 8, (uint32_t)((j / SLOTS) & 1));
        uint32_t sb = base + (uint32_t)s * CHB;

        uint32_t Ah[4], Al[4], Bh0[4], Bh1[4], Bl0[4], Bl1[4];
        ldm4(Ah,  sb + offAhi);
        ldm4(Al,  sb + offAlo);
        ldm4(Bh0, sb + offYh0);
        ldm4(Bh1, sb + offYh1);
        ldm4(Bl0, sb + offYl0);
        ldm4(Bl1, sb + offYl1);

        mma_(Cm[0], Ah, Bh0[0], Bh0[1]);
        mma_(Cm[1], Ah, Bh0[2], Bh0[3]);
        mma_(Cm[2], Ah, Bh1[0], Bh1[1]);
        mma_(Cm[3], Ah, Bh1[2], Bh1[3]);

        mma_(Cs[0], Ah, Bl0[0], Bl0[1]);
        mma_(Cs[1], Ah, Bl0[2], Bl0[3]);
        mma_(Cs[2], Ah, Bl1[0], Bl1[1]);
        mma_(Cs[3], Ah, Bl1[2], Bl1[3]);

        mma_(Cs[0], Al, Bh0[0], Bh0[1]);
        mma_(Cs[1], Al, Bh0[2], Bh0[3]);
        mma_(Cs[2], Al, Bh1[0], Bh1[1]);
        mma_(Cs[3], Al, Bh1[2], Bh1[3]);
    }
    __syncthreads();

    // scatter C frags -> sZ[c][m]  (overlay on drained pipeline smem)
    float (*sZ)[33] = (float (*)[33])sBuf;
    {
        const int g = lane >> 2, i2 = (lane & 3) << 1;
        const int cc = w * 16 + g;
        #pragma unroll
        for (int j = 0; j < 4; j++) {
            int m = j * 8 + i2;
            sZ[cc][m]         = Cm[j][0] + Cs[j][0] * INV2048;
            sZ[cc][m + 1]     = Cm[j][1] + Cs[j][1] * INV2048;
            sZ[cc + 8][m]     = Cm[j][2] + Cs[j][2] * INV2048;
            sZ[cc + 8][m + 1] = Cm[j][3] + Cs[j][3] * INV2048;
        }
    }
    __syncthreads();

    // store partial Z (coalesced float4, 16 floats per thread)
    {
        float* gp = &g_Zp[((size_t)(sp * NB + nb)) * 4096];
        #pragma unroll
        for (int q = 0; q < 4; q++) {
            int idx = t * 16 + q * 4;
            int cc = idx >> 5, m = idx & 31;
            float4 v = make_float4(sZ[cc][m], sZ[cc][m + 1], sZ[cc][m + 2], sZ[cc][m + 3]);
            *reinterpret_cast<float4*>(gp + idx) = v;
        }
    }
    __threadfence();
    __syncthreads();
    if (t == 0) {
        int old = atomicAdd(&g_cnt[nb], 1);
        sLast = (old == KSPLIT - 1);
    }
    __syncthreads();
    if (!sLast) return;

    // ---- ticket CTA: reduce partials + epilogue ----
    float* sWp = (float*)(sBuf + 128 * 33 * 4);
    for (int i = t; i < MR * MR; i += 256) sWp[i] = g_Wp[i];
    __syncthreads();

    const int col = t >> 1, r0 = (t & 1) << 4;
    const int gcol = nb * BN + col;
    float z[16];
    #pragma unroll
    for (int q = 0; q < 4; q++) {
        float4 acc = make_float4(0.f, 0.f, 0.f, 0.f);
        #pragma unroll
        for (int s2 = 0; s2 < KSPLIT; s2++) {
            const float4* p = reinterpret_cast<const float4*>(
                &g_Zp[((size_t)(s2 * NB + nb)) * 4096 + col * 32 + r0 + q * 4]);
            float4 v = __ldcg(p);
            acc.x += v.x; acc.y += v.y; acc.z += v.z; acc.w += v.w;
        }
        z[q * 4 + 0] = acc.x; z[q * 4 + 1] = acc.y;
        z[q * 4 + 2] = acc.z; z[q * 4 + 3] = acc.w;
    }

    float* Bp = &g_B[(nb * BN + col) * MR];
    const bool writeOut = (it == fwv);
    const bool writeY   = (it < fwv);

    #pragma unroll
    for (int r = 0; r < 16; r++) {
        int rr = r0 + r;
        float zz = z[r];
        if (useB)   zz += Bp[rr];
        if (writeB) Bp[rr] = zz;
        float xv = fmaxf(zz, 0.0f);
        if (writeOut && gcol < NCOLS) out[(size_t)rr * NCOLS + gcol] = xv;
        sZ[col][rr] = xv;
    }
    __syncthreads();

    if (writeY) {
        int kc = gcol >> 4, kk = gcol & 15;
        __half* Yd = g_Yp[src ^ 1] + (size_t)kc * 1024;
        #pragma unroll
        for (int r = 0; r < 16; r++) {
            int rr = r0 + r;
            float y = 0.f;
            #pragma unroll
            for (int j = 0; j < MR; j++) y += sWp[rr * MR + j] * sZ[col][j];
            __half h, l; hilo(y, h, l);
            Yd[rr * 16 + kk] = h;
            Yd[512 + rr * 16 + kk] = l;
        }
    }
    if (t == 0) g_cnt[nb] = 0;   // reset for next pass / replay
}

// ---------------- launch ----------------
// Inputs: W, Omega_1, Omega_2, X_0, A, U, fw_mitr
extern "C" void kernel_launch(void* const* d_in, const int* in_sizes, int n_in,
                              void* d_out, int out_size) {
    const float* W   = (const float*)d_in[0];
    const float* Om1 = (const float*)d_in[1];
    const float* A   = (const float*)d_in[4];
    const float* U   = (const float*)d_in[5];
    const int*   fw  = (const int*)  d_in[6];
    float*       out = (float*)d_out;

    static int attrDone = 0;
    if (!attrDone) {
        cudaFuncSetAttribute(k_iter, cudaFuncAttributeMaxDynamicSharedMemorySize, SMEMSZ);
        attrDone = 1;
    }

    k_project<<<1, 32>>>(W);
    k_convA<<<NB * KCH, 128>>>(A);
    k_T<<<KCH, 128>>>(Om1, U);

    // it = 1: Z = T@A = b ; B := Z ; X1 = relu(b) ; Y1 = Wp@X1
    k_iter<<<NB * KSPLIT, 256, SMEMSZ>>>(fw, out, 1, 0, 1, 0);
    // it = 2..30
    for (int it = 2; it <= 30; it++)
        k_iter<<<NB * KSPLIT, 256, SMEMSZ>>>(fw, out, it, (it - 1) & 1, 0, 1);
}

// round 17
// speedup vs baseline: 1.4240x; 1.0106x over previous
#include <cuda_runtime.h>
#include <cuda_fp16.h>
#include <cstdint>

#define MR     32
#define NCOLS  10000
#define NB     79         // column blocks of 128 (79*128 = 10112 padded)
#define BN     128
#define KCH    625        // k-chunks of 16
#define NPCH   632        // padded chunk count for Y buffers
#define KSPLIT 16
#define GROUP  5
#define SLOTS  10
#define CHB    10240      // chunk bytes in smem: A 8192 + Y 2048
#define SMEMSZ (SLOTS * CHB)       // 102400
#define INV2048 (1.0f/2048.0f)

// swizzled half-offset within a packed [rows x 16k] hi/lo region:
// element (row, kk) -> row*16 + ((kk>>3) ^ ((row>>2)&1))*8 + (kk&7)
#define SWZH(row, kk) ((row) * 16 + ((((kk) >> 3) ^ (((row) >> 2) & 1)) << 3) + ((kk) & 7))

// ---------------- device scratch (allocation-free) ----------------
// per (nb,kc) chunk: 2048 hi halves swizzled, then 2048 lo.  8 KB contiguous.
__device__ __align__(16) __half g_Apk[(size_t)NB * KCH * 4096];   // ~404 MB
// per kc: 512 hi halves swizzled, then 512 lo.  2 KB contiguous.
__device__ __align__(16) __half g_Yp[2][(size_t)NPCH * 1024];
__device__ __align__(16) float  g_Zp[(size_t)KSPLIT * NB * 4096];
__device__ float  g_B[NB * BN * MR];
__device__ float  g_Wp[MR * MR];
__device__ int    g_cnt[NB];                                      // zero-init; self-resetting

// ---------------- helpers ----------------
__device__ __forceinline__ void ldm4(uint32_t* r, uint32_t a) {
    asm volatile("ldmatrix.sync.aligned.m8n8.x4.shared.b16 {%0,%1,%2,%3}, [%4];"
        : "=r"(r[0]), "=r"(r[1]), "=r"(r[2]), "=r"(r[3]) : "r"(a));
}
__device__ __forceinline__ void mma_(float* c, const uint32_t* a, uint32_t b0, uint32_t b1) {
    asm volatile("mma.sync.aligned.m16n8k16.row.col.f32.f16.f16.f32 "
        "{%0,%1,%2,%3}, {%4,%5,%6,%7}, {%8,%9}, {%0,%1,%2,%3};"
        : "+f"(c[0]), "+f"(c[1]), "+f"(c[2]), "+f"(c[3])
        : "r"(a[0]), "r"(a[1]), "r"(a[2]), "r"(a[3]), "r"(b0), "r"(b1));
}
__device__ __forceinline__ void hilo(float v, __half& h, __half& l) {
    h = __float2half_rn(v);
    l = __float2half_rn((v - __half2float(h)) * 2048.0f);
}
__device__ __forceinline__ void bulk_ld(uint32_t dst, const void* src, uint32_t bytes, uint32_t mbar) {
    asm volatile(
        "cp.async.bulk.shared::cluster.global.mbarrier::complete_tx::bytes [%0], [%1], %2, [%3];"
        :: "r"(dst), "l"(src), "r"(bytes), "r"(mbar) : "memory");
}
__device__ __forceinline__ void mbar_wait(uint32_t mbar, uint32_t parity) {
    uint32_t done;
    asm volatile(
        "{\n\t.reg .pred p;\n\t"
        "mbarrier.try_wait.parity.acquire.cta.shared::cta.b64 p, [%1], %2;\n\t"
        "selp.b32 %0, 1, 0, p;\n\t}"
        : "=r"(done) : "r"(mbar), "r"(parity) : "memory");
    if (!done) {
        asm volatile(
            "{\n\t.reg .pred P1;\n\t"
            "W_%=:\n\t"
            "mbarrier.try_wait.parity.acquire.cta.shared::cta.b64 P1, [%0], %1, 0x989680;\n\t"
            "@P1 bra.uni D_%=;\n\t"
            "bra.uni W_%=;\n\t"
            "D_%=:\n\t}"
            :: "r"(mbar), "r"(parity) : "memory");
    }
}

// ---------------- 1. W projection (verified) ----------------
__global__ void k_project(const float* __restrict__ W) {
    int r = threadIdx.x;
    if (r >= MR) return;
    float a[32], u[32];
    float s = 0.0f;
    for (int i = 0; i < 32; i++) { a[i] = W[r * 32 + i]; u[i] = fabsf(a[i]); s += u[i]; }
    const float v = 0.99f;
    if (s > v) {
        for (int i = 1; i < 32; i++) {
            float key = u[i]; int j = i - 1;
            while (j >= 0 && u[j] < key) { u[j + 1] = u[j]; j--; }
            u[j + 1] = key;
        }
        float cs = 0.0f; int rho = 0;
        for (int i = 0; i < 32; i++) {
            cs += u[i];
            if (u[i] - (cs - v) / (float)(i + 1) > 0.0f) rho++;
        }
        float cs2 = 0.0f;
        for (int i = 0; i < rho; i++) cs2 += u[i];
        float theta = (cs2 - v) / (float)rho;
        for (int i = 0; i < 32; i++) {
            float m = fmaxf(fabsf(a[i]) - theta, 0.0f);
            a[i] = (a[i] > 0.0f) ? m : ((a[i] < 0.0f) ? -m : 0.0f);
        }
    }
    for (int i = 0; i < 32; i++) g_Wp[r * 32 + i] = a[i];
}

// ---------------- 2. Convert A -> packed swizzled fp16 hi/lo ----------------
__global__ void k_convA(const float* __restrict__ A) {
    __shared__ __align__(16) float sA[16][132];
    int b  = blockIdx.x;               // nb*KCH + kc
    int nb = b / KCH, kc = b % KCH;
    int t  = threadIdx.x;
    int k0 = kc * 16, c0 = nb * BN;
    for (int e = t; e < 2048; e += 128) {
        int kk = e >> 7, c = e & 127;
        int gc = c0 + c;
        float v0 = 0.0f;
        if (gc < NCOLS) v0 = A[(size_t)(k0 + kk) * NCOLS + gc];
        sA[kk][c] = v0;
    }
    __syncthreads();
    __half* dst = &g_Apk[(size_t)b * 4096];
    for (int e = t; e < 2048; e += 128) {
        int c = e >> 4, kk = e & 15;
        __half h, l; hilo(sA[kk][c], h, l);
        int idx = SWZH(c, kk);
        dst[idx] = h;
        dst[2048 + idx] = l;
    }
}

// ---------------- 3. T = Omega_1 @ U -> Y[0] packed swizzled ----------------
__global__ void k_T(const float* __restrict__ Om1, const float* __restrict__ U) {
    __shared__ float sOm[MR * 64];
    int t = threadIdx.x;
    for (int i = t; i < MR * 64; i += 128) sOm[i] = Om1[i];
    __syncthreads();
    int kc = blockIdx.x;
    __half* dst = &g_Yp[0][(size_t)kc * 1024];
    for (int e = t; e < 512; e += 128) {
        int m = e >> 4, kk = e & 15;
        int k = kc * 16 + kk;
        float v = 0.f;
        #pragma unroll
        for (int p = 0; p < 64; p++) v += sOm[m * 64 + p] * U[(size_t)p * NCOLS + k];
        __half h, l; hilo(v, h, l);
        int idx = SWZH(m, kk);
        dst[idx] = h;
        dst[512 + idx] = l;
    }
}

// ---------------- 4. Fused Picard pass: 4 warps x 32 cols, swizzled ----------
__global__ void __launch_bounds__(128, 2)
k_iter(const int* __restrict__ fw, float* __restrict__ out,
       int it, int src, int writeB, int useB) {
    extern __shared__ __align__(1024) unsigned char sBuf[];   // SMEMSZ dynamic
    __shared__ __align__(8) unsigned long long sFull[SLOTS];
    __shared__ int sLast;

    const int t = threadIdx.x;
    const int nb = blockIdx.x % NB;
    const int sp = blockIdx.x / NB;
    const int w = t >> 5, lane = t & 31;     // 4 warps, warp owns A-cols w*32..+31

    const int fwv = *fw;
    if (it > fwv) return;

    const int kbeg = (sp * KCH) / KSPLIT;
    const int kend = ((sp + 1) * KCH) / KSPLIT;
    const int len  = kend - kbeg;

    const __half* Asrc = &g_Apk[(size_t)nb * KCH * 4096];
    const __half* Ysrc = g_Yp[src];
    const uint32_t base = (uint32_t)__cvta_generic_to_shared(sBuf);
    const uint32_t mb0  = (uint32_t)__cvta_generic_to_shared(&sFull[0]);

    if (t == 0) {
        #pragma unroll
        for (int s = 0; s < SLOTS; s++)
            asm volatile("mbarrier.init.shared.b64 [%0], %1;"
                :: "r"(mb0 + s * 8), "r"(1u) : "memory");
    }
    __syncthreads();

    auto issueChunk = [&](int q) {           // local chunk index
        if (q >= len) return;
        int s = q % SLOTS;
        uint32_t sb = base + (uint32_t)s * CHB;
        uint32_t mb = mb0 + s * 8;
        asm volatile("mbarrier.arrive.expect_tx.shared.b64 _, [%0], %1;"
            :: "r"(mb), "r"((uint32_t)CHB) : "memory");
        bulk_ld(sb,        Asrc + (size_t)(kbeg + q) * 4096, 8192, mb);
        bulk_ld(sb + 8192, Ysrc + (size_t)(kbeg + q) * 1024, 2048, mb);
    };

    if (t == 0)
        for (int q = 0; q < 2 * GROUP; q++) issueChunk(q);

    // ldmatrix per-lane byte offsets (swizzled: sub ^= (row>>2)&1)
    const int tl = lane >> 3, rl = lane & 7;
    const int aRow = w * 32 + ((tl & 1) << 3) + rl;     // u=0 subtile rows
    const int aSub = ((tl >> 1) ^ (aRow >> 2)) & 1;
    const uint32_t offA = (uint32_t)(aRow * 32 + aSub * 16);
    const int yM = ((tl >> 1) << 3) + rl;
    const int ySub = ((tl & 1) ^ (yM >> 2)) & 1;
    const uint32_t offY = 8192u + (uint32_t)(yM * 32 + ySub * 16);
    // derived: u=1 rows +16 -> +512B (swizzle bit unchanged); lo regions at fixed offsets

    float Cm[8][4], Cs[8][4];
    #pragma unroll
    for (int j = 0; j < 8; j++)
        #pragma unroll
        for (int q = 0; q < 4; q++) { Cm[j][q] = 0.f; Cs[j][q] = 0.f; }

    for (int j = 0; j < len; j++) {
        if (j > 0 && (j % GROUP) == 0) {
            __syncthreads();                 // previous group's slots fully consumed
            if (t == 0)
                for (int q = j + GROUP; q < j + 2 * GROUP; q++) issueChunk(q);
        }
        int s = j % SLOTS;
        mbar_wait(mb0 + s * 8, (uint32_t)((j / SLOTS) & 1));
        uint32_t sb = base + (uint32_t)s * CHB;

        uint32_t Ah0[4], Ah1[4], Al0[4], Al1[4], Bh0[4], Bh1[4], Bl0[4], Bl1[4];
        ldm4(Ah0, sb + offA);
        ldm4(Ah1, sb + offA + 512);
        ldm4(Al0, sb + offA + 4096);
        ldm4(Al1, sb + offA + 4608);
        ldm4(Bh0, sb + offY);
        ldm4(Bh1, sb + offY + 512);
        ldm4(Bl0, sb + offY + 1024);
        ldm4(Bl1, sb + offY + 1536);

        mma_(Cm[0], Ah0, Bh0[0], Bh0[1]);
        mma_(Cm[1], Ah0, Bh0[2], Bh0[3]);
        mma_(Cm[2], Ah0, Bh1[0], Bh1[1]);
        mma_(Cm[3], Ah0, Bh1[2], Bh1[3]);
        mma_(Cm[4], Ah1, Bh0[0], Bh0[1]);
        mma_(Cm[5], Ah1, Bh0[2], Bh0[3]);
        mma_(Cm[6], Ah1, Bh1[0], Bh1[1]);
        mma_(Cm[7], Ah1, Bh1[2], Bh1[3]);

        mma_(Cs[0], Ah0, Bl0[0], Bl0[1]);
        mma_(Cs[1], Ah0, Bl0[2], Bl0[3]);
        mma_(Cs[2], Ah0, Bl1[0], Bl1[1]);
        mma_(Cs[3], Ah0, Bl1[2], Bl1[3]);
        mma_(Cs[4], Ah1, Bl0[0], Bl0[1]);
        mma_(Cs[5], Ah1, Bl0[2], Bl0[3]);
        mma_(Cs[6], Ah1, Bl1[0], Bl1[1]);
        mma_(Cs[7], Ah1, Bl1[2], Bl1[3]);

        mma_(Cs[0], Al0, Bh0[0], Bh0[1]);
        mma_(Cs[1], Al0, Bh0[2], Bh0[3]);
        mma_(Cs[2], Al0, Bh1[0], Bh1[1]);
        mma_(Cs[3], Al0, Bh1[2], Bh1[3]);
        mma_(Cs[4], Al1, Bh0[0], Bh0[1]);
        mma_(Cs[5], Al1, Bh0[2], Bh0[3]);
        mma_(Cs[6], Al1, Bh1[0], Bh1[1]);
        mma_(Cs[7], Al1, Bh1[2], Bh1[3]);
    }
    __syncthreads();

    // scatter C frags -> sZ[c][m]  (overlay on drained pipeline smem)
    float (*sZ)[33] = (float (*)[33])sBuf;
    {
        const int g = lane >> 2, i2 = (lane & 3) << 1;
        #pragma unroll
        for (int u = 0; u < 2; u++) {
            const int cc = w * 32 + u * 16 + g;
            #pragma unroll
            for (int j = 0; j < 4; j++) {
                int m = j * 8 + i2;
                float* cm = Cm[u * 4 + j];
                float* cs = Cs[u * 4 + j];
                sZ[cc][m]         = cm[0] + cs[0] * INV2048;
                sZ[cc][m + 1]     = cm[1] + cs[1] * INV2048;
                sZ[cc + 8][m]     = cm[2] + cs[2] * INV2048;
                sZ[cc + 8][m + 1] = cm[3] + cs[3] * INV2048;
            }
        }
    }
    __syncthreads();

    // store partial Z (coalesced float4, 32 floats per thread)
    {
        float* gp = &g_Zp[((size_t)(sp * NB + nb)) * 4096];
        #pragma unroll
        for (int q = 0; q < 8; q++) {
            int idx = q * 512 + t * 4;
            int cc = idx >> 5, m = idx & 31;
            float4 v = make_float4(sZ[cc][m], sZ[cc][m + 1], sZ[cc][m + 2], sZ[cc][m + 3]);
            *reinterpret_cast<float4*>(gp + idx) = v;
        }
    }
    __threadfence();
    __syncthreads();
    if (t == 0) {
        int old = atomicAdd(&g_cnt[nb], 1);
        sLast = (old == KSPLIT - 1);
    }
    __syncthreads();
    if (!sLast) return;

    // ---- ticket CTA: reduce partials + epilogue (1 thread per column) ----
    float* sWp = (float*)(sBuf + 128 * 33 * 4);
    for (int i = t; i < MR * MR; i += 128) sWp[i] = g_Wp[i];
    __syncthreads();

    const int col = t;
    const int gcol = nb * BN + col;
    float* Bp = &g_B[(nb * BN + col) * MR];
    const bool writeOut = (it == fwv);
    const bool writeY   = (it < fwv);

    #pragma unroll
    for (int h = 0; h < 2; h++) {
        const int r0 = h * 16;
        float z[16];
        #pragma unroll
        for (int q = 0; q < 4; q++) {
            float4 acc = make_float4(0.f, 0.f, 0.f, 0.f);
            #pragma unroll
            for (int s2 = 0; s2 < KSPLIT; s2++) {
                const float4* p = reinterpret_cast<const float4*>(
                    &g_Zp[((size_t)(s2 * NB + nb)) * 4096 + col * 32 + r0 + q * 4]);
                float4 v = __ldcg(p);
                acc.x += v.x; acc.y += v.y; acc.z += v.z; acc.w += v.w;
            }
            z[q * 4 + 0] = acc.x; z[q * 4 + 1] = acc.y;
            z[q * 4 + 2] = acc.z; z[q * 4 + 3] = acc.w;
        }
        #pragma unroll
        for (int r = 0; r < 16; r++) {
            int rr = r0 + r;
            float zz = z[r];
            if (useB)   zz += Bp[rr];
            if (writeB) Bp[rr] = zz;
            float xv = fmaxf(zz, 0.0f);
            if (writeOut && gcol < NCOLS) out[(size_t)rr * NCOLS + gcol] = xv;
            sZ[col][rr] = xv;
        }
    }
    __syncthreads();

    if (writeY) {
        int kc = gcol >> 4, kk = gcol & 15;
        __half* Yd = g_Yp[src ^ 1] + (size_t)kc * 1024;
        #pragma unroll
        for (int r = 0; r < 32; r++) {
            float y = 0.f;
            #pragma unroll
            for (int j = 0; j < MR; j++) y += sWp[r * MR + j] * sZ[col][j];
            __half h, l; hilo(y, h, l);
            int idx = SWZH(r, kk);
            Yd[idx] = h;
            Yd[512 + idx] = l;
        }
    }
    if (t == 0) g_cnt[nb] = 0;   // reset for next pass / replay
}

// ---------------- launch ----------------
// Inputs: W, Omega_1, Omega_2, X_0, A, U, fw_mitr
extern "C" void kernel_launch(void* const* d_in, const int* in_sizes, int n_in,
                              void* d_out, int out_size) {
    const float* W   = (const float*)d_in[0];
    const float* Om1 = (const float*)d_in[1];
    const float* A   = (const float*)d_in[4];
    const float* U   = (const float*)d_in[5];
    const int*   fw  = (const int*)  d_in[6];
    float*       out = (float*)d_out;

    static int attrDone = 0;
    if (!attrDone) {
        cudaFuncSetAttribute(k_iter, cudaFuncAttributeMaxDynamicSharedMemorySize, SMEMSZ);
        attrDone = 1;
    }

    k_project<<<1, 32>>>(W);
    k_convA<<<NB * KCH, 128>>>(A);
    k_T<<<KCH, 128>>>(Om1, U);

    // it = 1: Z = T@A = b ; B := Z ; X1 = relu(b) ; Y1 = Wp@X1
    k_iter<<<NB * KSPLIT, 128, SMEMSZ>>>(fw, out, 1, 0, 1, 0);
    // it = 2..30
    for (int it = 2; it <= 30; it++)
        k_iter<<<NB * KSPLIT, 128, SMEMSZ>>>(fw, out, it, (it - 1) & 1, 0, 1);
}